// round 10
// baseline (speedup 1.0000x reference)
#include <cuda_runtime.h>
#include <cuda_fp16.h>
#include <math.h>

#define PI_F 3.14159265358979323846f
#define MARGIN_F 9.0f

#define DIM 512
#define HALF 256
#define NUM_REL 64
#define MAX_NODES 100000
#define ROT_BLOCKS 64   // first blocks of prep kernel build the rot tables

// Chunk-interleaved fp16 node table: row = 32 chunks of 32B;
// chunk k = re[8k..8k+8) ++ im[8k..8k+8).  100000 rows x 1KB = 102.4 MB.
__device__ __half g_nodesP[(size_t)MAX_NODES * DIM];

// Fused rot table, same chunking: per relation 32 chunks of 32B;
// chunk k = cos[8k..8k+8) ++ sin[8k..8k+8).  64 KB total.
__device__ __half g_rotP[NUM_REL * DIM];

// Precomputed epilogue constants: out = fmaf(acc, g_scale, g_bias)
__device__ float g_scale;
__device__ float g_bias;

// ---- policy + hinted memory ops ----
__device__ __forceinline__ unsigned long long mk_evict_last_policy() {
    unsigned long long p;
    asm("createpolicy.fractional.L2::evict_last.b64 %0, 1.0;" : "=l"(p));
    return p;
}
// 256-bit global load with L2 evict-last hint.
__device__ __forceinline__ void ldg256_hint(const void* p, unsigned long long pol,
                                            uint4& a, uint4& b) {
    asm("ld.global.L2::cache_hint.v8.b32 {%0,%1,%2,%3,%4,%5,%6,%7}, [%8], %9;"
        : "=r"(a.x), "=r"(a.y), "=r"(a.z), "=r"(a.w),
          "=r"(b.x), "=r"(b.y), "=r"(b.z), "=r"(b.w)
        : "l"(p), "l"(pol));
}
__device__ __forceinline__ void stg256_hint(void* p, unsigned long long pol,
                                            uint4 a, uint4 b) {
    asm volatile("st.global.L2::cache_hint.v8.b32 [%0], {%1,%2,%3,%4,%5,%6,%7,%8}, %9;"
        :: "l"(p), "r"(a.x), "r"(a.y), "r"(a.z), "r"(a.w),
           "r"(b.x), "r"(b.y), "r"(b.z), "r"(b.w), "l"(pol) : "memory");
}
__device__ __forceinline__ float4 ldg_streaming_f4(const float4* p) {
    float4 v;
    asm("ld.global.cs.v4.f32 {%0,%1,%2,%3}, [%4];"
        : "=f"(v.x), "=f"(v.y), "=f"(v.z), "=f"(v.w) : "l"(p));
    return v;
}
__device__ __forceinline__ float sqrt_approx(float x) {
    float r;
    asm("sqrt.approx.f32 %0, %1;" : "=f"(r) : "f"(x));
    return r;
}
__device__ __forceinline__ unsigned pack2(float lo, float hi) {
    __half2 h = __floats2half2_rn(lo, hi);
    return *(unsigned*)&h;
}

// Fused prep: blocks [0,ROT_BLOCKS) build rot tables + epilogue constants;
// the rest convert+permute the fp32 node table to chunk-interleaved fp16.
// One convert thread per 32B output chunk.
__global__ void __launch_bounds__(256)
prep_kernel(const float* __restrict__ relation_emb,
            const float* __restrict__ nodes,
            const float* __restrict__ temperature,
            const float* __restrict__ bias,
            long long n_chunks) {
    if (blockIdx.x < ROT_BLOCKS) {
        int i = blockIdx.x * blockDim.x + threadIdx.x;
        if (i == 0) {
            g_scale = -1.0f / ((float)HALF * temperature[0]);
            g_bias  = bias[0];
        }
        if (i < NUM_REL * HALF) {
            int r = i >> 8;          // relation
            int j = i & 255;         // element within half-dim
            float phase = relation_emb[i] * (PI_F / MARGIN_F);
            float s, c;
            sincosf(phase, &s, &c);
            // chunk k = j/8 holds cos at [0..8), sin at [8..16) within 16 halfs
            int base = r * DIM + (j >> 3) * 16 + (j & 7);
            g_rotP[base]     = __float2half_rn(c);
            g_rotP[base + 8] = __float2half_rn(s);
        }
        return;
    }
    long long i = (long long)(blockIdx.x - ROT_BLOCKS) * blockDim.x + threadIdx.x;
    if (i >= n_chunks) return;   // chunk index: node = i/32, k = i%32
    long long node = i >> 5;
    int k = (int)(i & 31);
    const float4* src = (const float4*)(nodes + node * DIM);
    // re[8k..8k+8) = float4s [2k, 2k+1]; im = float4s [64+2k, 64+2k+1]
    float4 r0 = ldg_streaming_f4(&src[2 * k]);
    float4 r1 = ldg_streaming_f4(&src[2 * k + 1]);
    float4 i0 = ldg_streaming_f4(&src[64 + 2 * k]);
    float4 i1 = ldg_streaming_f4(&src[64 + 2 * k + 1]);
    uint4 a, b;
    a.x = pack2(r0.x, r0.y); a.y = pack2(r0.z, r0.w);
    a.z = pack2(r1.x, r1.y); a.w = pack2(r1.z, r1.w);
    b.x = pack2(i0.x, i0.y); b.y = pack2(i0.z, i0.w);
    b.z = pack2(i1.x, i1.y); b.w = pack2(i1.z, i1.w);
    unsigned long long pol = mk_evict_last_policy();
    stg256_hint((char*)g_nodesP + i * 32, pol, a, b);
}

// One edge's partial distance sum for this lane: 3 x 256-bit loads.
__device__ __forceinline__ float edge_partial(long long h, long long t, int r,
                                              int laneB, unsigned long long pol) {
    uint4 reh, imh, ret, imt, crr, srr;
    ldg256_hint((const char*)g_nodesP + (h << 10) + laneB, pol, reh, imh);
    ldg256_hint((const char*)g_nodesP + (t << 10) + laneB, pol, ret, imt);
    ldg256_hint((const char*)g_rotP + ((long long)r << 10) + laneB, pol, crr, srr);

    const unsigned* rh_w = &reh.x;
    const unsigned* ih_w = &imh.x;
    const unsigned* rt_w = &ret.x;
    const unsigned* it_w = &imt.x;
    const unsigned* cr_w = &crr.x;
    const unsigned* sr_w = &srr.x;

    float a0 = 0.0f, a1 = 0.0f;
    #pragma unroll
    for (int w = 0; w < 4; w++) {
        __half2 rh2 = *(const __half2*)&rh_w[w];
        __half2 ih2 = *(const __half2*)&ih_w[w];
        __half2 rt2 = *(const __half2*)&rt_w[w];
        __half2 it2 = *(const __half2*)&it_w[w];
        __half2 cr2 = *(const __half2*)&cr_w[w];
        __half2 sr2 = *(const __half2*)&sr_w[w];

        // re = rh*cr - (ih*sr + rt) ; im = rh*sr + (ih*cr - it)
        __half2 wv  = __hfma2(ih2, sr2, rt2);
        __half2 re2 = __hfma2(rh2, cr2, __hneg2(wv));
        __half2 im2 = __hfma2(rh2, sr2, __hfma2(ih2, cr2, __hneg2(it2)));
        __half2 d2  = __hfma2(re2, re2, __hmul2(im2, im2));

        float2 d = __half22float2(d2);
        a0 += sqrt_approx(d.x);
        a1 += sqrt_approx(d.y);
    }
    return a0 + a1;
}

// Two edges per warp; paired butterfly reduction (5 shuffles for both).
__global__ void __launch_bounds__(256)
rotate_score_kernel(const int* __restrict__ edge_index,
                    const int* __restrict__ rel_type,
                    float* __restrict__ out,
                    int num_edges) {
    int wp = (blockIdx.x * blockDim.x + threadIdx.x) >> 5;
    int lane = threadIdx.x & 31;
    int e0 = wp * 2;
    if (e0 >= num_edges) return;
    bool hasB = (e0 + 1) < num_edges;

    int hA, hB, tA, tB, rA, rB;
    if (hasB) {
        int2 hh = ((const int2*)edge_index)[wp];
        int2 tt = ((const int2*)(edge_index + num_edges))[wp];
        int2 rr = ((const int2*)rel_type)[wp];
        hA = hh.x; hB = hh.y; tA = tt.x; tB = tt.y; rA = rr.x; rB = rr.y;
    } else {
        hA = edge_index[e0]; tA = edge_index[num_edges + e0]; rA = rel_type[e0];
        hB = hA; tB = tA; rB = rA;
    }

    unsigned long long pol = mk_evict_last_policy();
    int laneB = lane * 32;   // byte offset of this lane's 32B chunk

    float sA = edge_partial((long long)hA, (long long)tA, rA, laneB, pol);
    float sB = edge_partial((long long)hB, (long long)tB, rB, laneB, pol);

    // Pair-combine: lanes 0-15 accumulate edge A, lanes 16-31 edge B.
    bool hi = (lane & 16) != 0;
    float send = hi ? sA : sB;
    float keep = hi ? sB : sA;
    float v = keep + __shfl_xor_sync(0xffffffffu, send, 16);
    #pragma unroll
    for (int off = 8; off > 0; off >>= 1)
        v += __shfl_xor_sync(0xffffffffu, v, off);

    float res = fmaf(v, g_scale, g_bias);
    if (lane == 0) out[e0] = res;
    if (lane == 16 && hasB) out[e0 + 1] = res;
}

extern "C" void kernel_launch(void* const* d_in, const int* in_sizes, int n_in,
                              void* d_out, int out_size) {
    const float* nodes       = (const float*)d_in[0];
    const int*   edge_index  = (const int*)d_in[1];
    const int*   rel_type    = (const int*)d_in[2];
    const float* rel_emb     = (const float*)d_in[3];
    const float* temperature = (const float*)d_in[4];
    const float* bias        = (const float*)d_in[5];
    float*       out         = (float*)d_out;

    int num_edges = in_sizes[2];
    long long n_chunks = (long long)in_sizes[0] / 16;  // 16 elems per 32B chunk

    int conv_blocks = (int)((n_chunks + 255) / 256);
    prep_kernel<<<ROT_BLOCKS + conv_blocks, 256>>>(rel_emb, nodes,
                                                   temperature, bias, n_chunks);

    int pairs = (num_edges + 1) / 2;
    int warps_per_block = 256 / 32;
    int blocks = (pairs + warps_per_block - 1) / warps_per_block;
    rotate_score_kernel<<<blocks, 256>>>(edge_index, rel_type, out, num_edges);
}